// round 6
// baseline (speedup 1.0000x reference)
#include <cuda_runtime.h>
#include <cstdint>

// ============================================================================
// QuantizedLinear: out = scale * (x @ S^T) + bias, S = sign(w)*(|w|>0.7*mean|w|)
// x [65536, 512] fp32, w [512, 512] fp32, bias [512] fp32, out [65536, 512] fp32
//
// mma.sync.m16n8k8.tf32 (compute_103: no tcgen05). BK=16, 64B smem rows.
// K-permutation: for mma step st, lane qc supplies physical k {4qc+st, 4qc+2+st}
// in both A and B fragments -> one LDS.128 per row covers both k-steps.
// R5 bug fix: cp.async wait_group 2 (= STAGES-2), not 3.
// ============================================================================
#define K_DIM 512
#define N_DIM 512
#define BM 128
#define BN 64
#define BK 16
#define KT (K_DIM / BK)      // 32
#define STAGES 4
#define THREADS 256

#define A_STAGE_BYTES (BM * BK * 4)                    // 8192
#define B_STAGE_BYTES (BN * BK * 4)                    // 4096
#define STAGE_BYTES   (A_STAGE_BYTES + B_STAGE_BYTES)  // 12288
#define SMEM_TOTAL    (STAGES * STAGE_BYTES)           // 49152 -> 3 CTAs/SM

// Scratch (allocation-free)
__device__ float  d_wq[N_DIM * K_DIM];
__device__ double d_partial[256];
__device__ float  d_scale;
__device__ float  d_thresh;

// ============================================================================
// Prep kernels
// ============================================================================
__global__ void k_abssum(const float* __restrict__ w) {
    __shared__ double s[256];
    int b = blockIdx.x, t = threadIdx.x;
    const float* p = w + b * 1024;
    double acc = (double)fabsf(p[t]) + (double)fabsf(p[t + 256]) +
                 (double)fabsf(p[t + 512]) + (double)fabsf(p[t + 768]);
    s[t] = acc;
    __syncthreads();
    for (int o = 128; o > 0; o >>= 1) {
        if (t < o) s[t] += s[t + o];
        __syncthreads();
    }
    if (t == 0) d_partial[b] = s[0];
}

__global__ void k_scale() {
    double tot = 0.0;
    for (int i = 0; i < 256; i++) tot += d_partial[i];
    float sc = (float)(tot / (double)(N_DIM * K_DIM));
    if (sc < 1e-8f) sc = 1e-8f;
    d_scale = sc;
    d_thresh = 0.7f * sc;
}

__global__ void k_quant(const float* __restrict__ w) {
    int i = blockIdx.x * blockDim.x + threadIdx.x;
    float v = w[i];
    float th = d_thresh;
    d_wq[i] = (fabsf(v) > th) ? (v > 0.0f ? 1.0f : -1.0f) : 0.0f;
}

// ============================================================================
// Helpers
// ============================================================================
__device__ __forceinline__ uint32_t smem_u32(const void* p) {
    uint32_t a;
    asm("{ .reg .u64 t; cvta.to.shared.u64 t, %1; cvt.u32.u64 %0, t; }"
        : "=r"(a) : "l"(p));
    return a;
}

__device__ __forceinline__ void cp16(uint32_t saddr, const void* gaddr) {
    asm volatile("cp.async.cg.shared.global [%0], [%1], 16;"
                 :: "r"(saddr), "l"(gaddr) : "memory");
}

__device__ __forceinline__ void cp_commit() {
    asm volatile("cp.async.commit_group;" ::: "memory");
}

__device__ __forceinline__ void cp_wait2() {
    asm volatile("cp.async.wait_group 2;" ::: "memory");
}

__device__ __forceinline__ void lds128f(float* r, uint32_t addr) {
    asm volatile("ld.shared.v4.b32 {%0,%1,%2,%3}, [%4];"
                 : "=f"(r[0]), "=f"(r[1]), "=f"(r[2]), "=f"(r[3]) : "r"(addr));
}

__device__ __forceinline__ void lds128u(uint32_t* r, uint32_t addr) {
    asm volatile("ld.shared.v4.b32 {%0,%1,%2,%3}, [%4];"
                 : "=r"(r[0]), "=r"(r[1]), "=r"(r[2]), "=r"(r[3]) : "r"(addr));
}

__device__ __forceinline__ uint32_t f2tf32(float f) {
    uint32_t r;
    asm("cvt.rna.tf32.f32 %0, %1;" : "=r"(r) : "f"(f));
    return r;
}

__device__ __forceinline__ void mma_tf32(float* c, uint32_t a0, uint32_t a1,
                                         uint32_t a2, uint32_t a3,
                                         uint32_t b0, uint32_t b1) {
    asm volatile(
        "mma.sync.aligned.m16n8k8.row.col.f32.tf32.tf32.f32 "
        "{%0,%1,%2,%3}, {%4,%5,%6,%7}, {%8,%9}, {%0,%1,%2,%3};"
        : "+f"(c[0]), "+f"(c[1]), "+f"(c[2]), "+f"(c[3])
        : "r"(a0), "r"(a1), "r"(a2), "r"(a3), "r"(b0), "r"(b1));
}

// ============================================================================
// Main GEMM: block 128x64, 8 warps (4M x 2N), warp tile 32x32
// ============================================================================
__global__ void __launch_bounds__(THREADS, 3) gemm_tf32(
    const float* __restrict__ x,
    const float* __restrict__ bias,
    float* __restrict__ out)
{
    extern __shared__ float smem[];
    const uint32_t sb = smem_u32(smem);
    const int tid = threadIdx.x;
    const int wid = tid >> 5;
    const int lane = tid & 31;
    const int grp = lane >> 2;     // 0..7
    const int qc = lane & 3;       // 0..3

    // 8 N-tiles of 64; consecutive bids share the M-tile (A L2 reuse)
    const int ntile = blockIdx.x & 7;
    const int mtile = blockIdx.x >> 3;
    const int m0 = mtile * BM;
    const int n0 = ntile * BN;

    const int warp_m = (wid & 3) * 32;          // 4 warps along M
    const int warp_n = (wid >> 2) * 32;         // 2 warps along N

    const float* wq = d_wq;

    // ---- cp.async loader: straight copy, 64B rows ----
    auto load_stage = [&](int s, int kt) {
        const uint32_t sA = sb + s * STAGE_BYTES;
        const uint32_t sB = sA + A_STAGE_BYTES;
        const int kk = kt * BK;
        #pragma unroll
        for (int i = 0; i < 2; i++) {
            int c = tid + i * THREADS;
            int row = c >> 2, cc = c & 3;
            cp16(sA + (uint32_t)c * 16,
                 x + (size_t)(m0 + row) * K_DIM + kk + cc * 4);
        }
        {
            int row = tid >> 2, cc = tid & 3;
            cp16(sB + (uint32_t)tid * 16,
                 wq + (size_t)(n0 + row) * K_DIM + kk + cc * 4);
        }
    };

    float acc[2][4][4];
    #pragma unroll
    for (int i = 0; i < 2; i++)
        #pragma unroll
        for (int j = 0; j < 4; j++)
            #pragma unroll
            for (int r = 0; r < 4; r++) acc[i][j][r] = 0.0f;

    load_stage(0, 0);
    cp_commit();
    load_stage(1, 1);
    cp_commit();
    load_stage(2, 2);
    cp_commit();

    const uint32_t fragA_off = (uint32_t)(warp_m + grp) * 64 + (uint32_t)qc * 16;
    const uint32_t fragB_off = (uint32_t)(warp_n + grp) * 64 + (uint32_t)qc * 16;

    for (int kt = 0; kt < KT; kt++) {
        cp_wait2();                 // committed = 3+kt; <=2 pending => stage kt done
        __syncthreads();

        if (kt + 3 < KT) load_stage((kt + 3) & 3, kt + 3);
        cp_commit();

        const int s = kt & 3;
        const uint32_t sA = sb + s * STAGE_BYTES;
        const uint32_t sB = sA + A_STAGE_BYTES;

        // ---- fragments: 4 A-row LDS.128 + 4 B-row LDS.128 per warp ----
        float a00[4], a01[4], a10[4], a11[4];
        uint32_t b0[4], b1[4], b2[4], b3[4];
        lds128f(a00, sA + fragA_off);                 // row warp_m+grp
        lds128f(a01, sA + fragA_off + 8 * 64);        // +8
        lds128f(a10, sA + fragA_off + 16 * 64);       // tm=1
        lds128f(a11, sA + fragA_off + 24 * 64);
        lds128u(b0, sB + fragB_off);                  // n = warp_n+grp (+0,8,16,24)
        lds128u(b1, sB + fragB_off + 8 * 64);
        lds128u(b2, sB + fragB_off + 16 * 64);
        lds128u(b3, sB + fragB_off + 24 * 64);

        // convert A to tf32 (rna); B is exact {-1,0,1}
        uint32_t ta00[4], ta01[4], ta10[4], ta11[4];
        #pragma unroll
        for (int e = 0; e < 4; e++) {
            ta00[e] = f2tf32(a00[e]);
            ta01[e] = f2tf32(a01[e]);
            ta10[e] = f2tf32(a10[e]);
            ta11[e] = f2tf32(a11[e]);
        }

        #pragma unroll
        for (int st = 0; st < 2; st++) {        // two k=8 steps
            const int e0 = st, e1 = st + 2;
            mma_tf32(acc[0][0], ta00[e0], ta01[e0], ta00[e1], ta01[e1], b0[e0], b0[e1]);
            mma_tf32(acc[0][1], ta00[e0], ta01[e0], ta00[e1], ta01[e1], b1[e0], b1[e1]);
            mma_tf32(acc[0][2], ta00[e0], ta01[e0], ta00[e1], ta01[e1], b2[e0], b2[e1]);
            mma_tf32(acc[0][3], ta00[e0], ta01[e0], ta00[e1], ta01[e1], b3[e0], b3[e1]);
            mma_tf32(acc[1][0], ta10[e0], ta11[e0], ta10[e1], ta11[e1], b0[e0], b0[e1]);
            mma_tf32(acc[1][1], ta10[e0], ta11[e0], ta10[e1], ta11[e1], b1[e0], b1[e1]);
            mma_tf32(acc[1][2], ta10[e0], ta11[e0], ta10[e1], ta11[e1], b2[e0], b2[e1]);
            mma_tf32(acc[1][3], ta10[e0], ta11[e0], ta10[e1], ta11[e1], b3[e0], b3[e1]);
        }
    }

    // ---- Epilogue: out = scale*acc + bias ----
    const float scale = d_scale;
    #pragma unroll
    for (int tm = 0; tm < 2; tm++) {
        #pragma unroll
        for (int tn = 0; tn < 4; tn++) {
            const int row = m0 + warp_m + tm * 16 + grp;
            const int col = n0 + warp_n + tn * 8 + qc * 2;
            const float2 bv = *reinterpret_cast<const float2*>(bias + col);
            float2 v0, v1;
            v0.x = fmaf(scale, acc[tm][tn][0], bv.x);
            v0.y = fmaf(scale, acc[tm][tn][1], bv.y);
            v1.x = fmaf(scale, acc[tm][tn][2], bv.x);
            v1.y = fmaf(scale, acc[tm][tn][3], bv.y);
            *reinterpret_cast<float2*>(out + (size_t)row * N_DIM + col) = v0;
            *reinterpret_cast<float2*>(out + (size_t)(row + 8) * N_DIM + col) = v1;
        }
    }
}

// ============================================================================
// Host
// ============================================================================
extern "C" void kernel_launch(void* const* d_in, const int* in_sizes, int n_in,
                              void* d_out, int out_size) {
    const float* x    = (const float*)d_in[0];
    const float* w    = (const float*)d_in[1];
    const float* bias = (const float*)d_in[2];
    float* out        = (float*)d_out;
    const int M = in_sizes[0] / K_DIM;   // 65536

    cudaFuncSetAttribute(gemm_tf32, cudaFuncAttributeMaxDynamicSharedMemorySize,
                         SMEM_TOTAL);

    k_abssum<<<256, 256>>>(w);
    k_scale<<<1, 1>>>();
    k_quant<<<(N_DIM * K_DIM) / 256, 256>>>(w);

    const int grid = (M / BM) * (N_DIM / BN);   // 512 * 8 = 4096
    gemm_tf32<<<grid, THREADS, SMEM_TOTAL>>>(x, bias, out);
}

// round 7
// speedup vs baseline: 1.6452x; 1.6452x over previous
#include <cuda_runtime.h>
#include <cstdint>

// ============================================================================
// QuantizedLinear: out = scale * (x @ S^T) + bias, S = sign(w)*(|w|>0.7*mean|w|)
// x [65536, 512] fp32, w [512, 512] fp32, bias [512] fp32, out [65536, 512] fp32
//
// mma.sync.m16n8k8.tf32 (compute_103: no tcgen05).
// R7: occupancy play. Block 128x64, warp 32x32, BK=32, scalar LDS (PAD 36),
// 2-stage cp.async, 55.3KB smem, <=84 regs -> 3 CTAs/SM (24 warps).
// ============================================================================
#define K_DIM 512
#define N_DIM 512
#define BM 128
#define BN 64
#define BK 32
#define KT (K_DIM / BK)      // 16
#define STAGES 2
#define PAD_K 36             // 144B rows: 16B-aligned, conflict-free scalar LDS
#define THREADS 256

#define A_STAGE_BYTES (BM * PAD_K * 4)                 // 18432
#define B_STAGE_BYTES (BN * PAD_K * 4)                 // 9216
#define STAGE_BYTES   (A_STAGE_BYTES + B_STAGE_BYTES)  // 27648
#define SMEM_TOTAL    (STAGES * STAGE_BYTES)           // 55296 -> 3 CTAs/SM

// Scratch (allocation-free)
__device__ float  d_wq[N_DIM * K_DIM];
__device__ double d_partial[256];
__device__ float  d_scale;
__device__ float  d_thresh;

// ============================================================================
// Prep kernels
// ============================================================================
__global__ void k_abssum(const float* __restrict__ w) {
    __shared__ double s[256];
    int b = blockIdx.x, t = threadIdx.x;
    const float* p = w + b * 1024;
    double acc = (double)fabsf(p[t]) + (double)fabsf(p[t + 256]) +
                 (double)fabsf(p[t + 512]) + (double)fabsf(p[t + 768]);
    s[t] = acc;
    __syncthreads();
    for (int o = 128; o > 0; o >>= 1) {
        if (t < o) s[t] += s[t + o];
        __syncthreads();
    }
    if (t == 0) d_partial[b] = s[0];
}

__global__ void k_scale() {
    double tot = 0.0;
    for (int i = 0; i < 256; i++) tot += d_partial[i];
    float sc = (float)(tot / (double)(N_DIM * K_DIM));
    if (sc < 1e-8f) sc = 1e-8f;
    d_scale = sc;
    d_thresh = 0.7f * sc;
}

__global__ void k_quant(const float* __restrict__ w) {
    int i = blockIdx.x * blockDim.x + threadIdx.x;
    float v = w[i];
    float th = d_thresh;
    d_wq[i] = (fabsf(v) > th) ? (v > 0.0f ? 1.0f : -1.0f) : 0.0f;
}

// ============================================================================
// Helpers
// ============================================================================
__device__ __forceinline__ uint32_t smem_u32(const void* p) {
    uint32_t a;
    asm("{ .reg .u64 t; cvta.to.shared.u64 t, %1; cvt.u32.u64 %0, t; }"
        : "=r"(a) : "l"(p));
    return a;
}

__device__ __forceinline__ void cp16(uint32_t saddr, const void* gaddr) {
    asm volatile("cp.async.cg.shared.global [%0], [%1], 16;"
                 :: "r"(saddr), "l"(gaddr) : "memory");
}

__device__ __forceinline__ void cp_commit() {
    asm volatile("cp.async.commit_group;" ::: "memory");
}

__device__ __forceinline__ void cp_wait0() {
    asm volatile("cp.async.wait_group 0;" ::: "memory");
}

__device__ __forceinline__ uint32_t f2tf32(float f) {
    uint32_t r;
    asm("cvt.rna.tf32.f32 %0, %1;" : "=r"(r) : "f"(f));
    return r;
}

__device__ __forceinline__ void mma_tf32(float* c, uint32_t a0, uint32_t a1,
                                         uint32_t a2, uint32_t a3,
                                         uint32_t b0, uint32_t b1) {
    asm volatile(
        "mma.sync.aligned.m16n8k8.row.col.f32.tf32.tf32.f32 "
        "{%0,%1,%2,%3}, {%4,%5,%6,%7}, {%8,%9}, {%0,%1,%2,%3};"
        : "+f"(c[0]), "+f"(c[1]), "+f"(c[2]), "+f"(c[3])
        : "r"(a0), "r"(a1), "r"(a2), "r"(a3), "r"(b0), "r"(b1));
}

// ============================================================================
// Main GEMM: block 128x64, 8 warps (4M x 2N), warp tile 32x32
// ============================================================================
__global__ void __launch_bounds__(THREADS, 3) gemm_tf32(
    const float* __restrict__ x,
    const float* __restrict__ bias,
    float* __restrict__ out)
{
    extern __shared__ float smem[];
    const uint32_t sb = smem_u32(smem);
    const int tid = threadIdx.x;
    const int wid = tid >> 5;
    const int lane = tid & 31;
    const int grp = lane >> 2;     // 0..7
    const int qc = lane & 3;       // 0..3

    // 8 N-tiles of 64; consecutive bids share the M-tile (A L2 reuse)
    const int ntile = blockIdx.x & 7;
    const int mtile = blockIdx.x >> 3;
    const int m0 = mtile * BM;
    const int n0 = ntile * BN;

    const int warp_m = (wid & 3) * 32;          // 4 warps along M
    const int warp_n = (wid >> 2) * 32;         // 2 warps along N

    const float* wq = d_wq;

    // ---- cp.async loader: A 1024 chunks + B 512 chunks, 6 per thread ----
    auto load_stage = [&](int s, int kt) {
        const uint32_t sA = sb + s * STAGE_BYTES;
        const uint32_t sB = sA + A_STAGE_BYTES;
        const int kk = kt * BK;
        #pragma unroll
        for (int i = 0; i < 4; i++) {
            int c = tid + i * THREADS;
            int row = c >> 3, cc = c & 7;
            cp16(sA + (uint32_t)row * (PAD_K * 4) + (uint32_t)cc * 16,
                 x + (size_t)(m0 + row) * K_DIM + kk + cc * 4);
        }
        #pragma unroll
        for (int i = 0; i < 2; i++) {
            int c = tid + i * THREADS;
            int row = c >> 3, cc = c & 7;
            cp16(sB + (uint32_t)row * (PAD_K * 4) + (uint32_t)cc * 16,
                 wq + (size_t)(n0 + row) * K_DIM + kk + cc * 4);
        }
    };

    float acc[2][4][4];
    #pragma unroll
    for (int i = 0; i < 2; i++)
        #pragma unroll
        for (int j = 0; j < 4; j++)
            #pragma unroll
            for (int r = 0; r < 4; r++) acc[i][j][r] = 0.0f;

    load_stage(0, 0);
    cp_commit();

    for (int kt = 0; kt < KT; kt++) {
        cp_wait0();                 // stage kt resident (all issued loads done)
        __syncthreads();            // visible to all; all reads of kt-1 done

        if (kt + 1 < KT) {          // overlap next load with compute(kt)
            load_stage((kt + 1) & 1, kt + 1);
            cp_commit();
        }

        const int s = kt & 1;
        const float* As = smem + s * (STAGE_BYTES / 4);
        const float* Bs = As + (A_STAGE_BYTES / 4);

        #pragma unroll
        for (int ks = 0; ks < 4; ks++) {   // four k=8 steps
            const int k0 = ks * 8;
            uint32_t a[2][4], b[4][2];
            #pragma unroll
            for (int tm = 0; tm < 2; tm++) {
                const float* ap = As + (warp_m + tm * 16 + grp) * PAD_K + k0 + qc;
                a[tm][0] = f2tf32(ap[0]);
                a[tm][1] = f2tf32(ap[8 * PAD_K]);
                a[tm][2] = f2tf32(ap[4]);
                a[tm][3] = f2tf32(ap[8 * PAD_K + 4]);
            }
            #pragma unroll
            for (int tn = 0; tn < 4; tn++) {
                const float* bp = Bs + (warp_n + tn * 8 + grp) * PAD_K + k0 + qc;
                b[tn][0] = __float_as_uint(bp[0]);   // S exact in tf32
                b[tn][1] = __float_as_uint(bp[4]);
            }
            #pragma unroll
            for (int tm = 0; tm < 2; tm++)
                #pragma unroll
                for (int tn = 0; tn < 4; tn++)
                    mma_tf32(acc[tm][tn], a[tm][0], a[tm][1], a[tm][2], a[tm][3],
                             b[tn][0], b[tn][1]);
        }
    }

    // ---- Epilogue: out = scale*acc + bias ----
    const float scale = d_scale;
    #pragma unroll
    for (int tm = 0; tm < 2; tm++) {
        #pragma unroll
        for (int tn = 0; tn < 4; tn++) {
            const int row = m0 + warp_m + tm * 16 + grp;
            const int col = n0 + warp_n + tn * 8 + qc * 2;
            const float2 bv = *reinterpret_cast<const float2*>(bias + col);
            float2 v0, v1;
            v0.x = fmaf(scale, acc[tm][tn][0], bv.x);
            v0.y = fmaf(scale, acc[tm][tn][1], bv.y);
            v1.x = fmaf(scale, acc[tm][tn][2], bv.x);
            v1.y = fmaf(scale, acc[tm][tn][3], bv.y);
            *reinterpret_cast<float2*>(out + (size_t)row * N_DIM + col) = v0;
            *reinterpret_cast<float2*>(out + (size_t)(row + 8) * N_DIM + col) = v1;
        }
    }
}

// ============================================================================
// Host
// ============================================================================
extern "C" void kernel_launch(void* const* d_in, const int* in_sizes, int n_in,
                              void* d_out, int out_size) {
    const float* x    = (const float*)d_in[0];
    const float* w    = (const float*)d_in[1];
    const float* bias = (const float*)d_in[2];
    float* out        = (float*)d_out;
    const int M = in_sizes[0] / K_DIM;   // 65536

    cudaFuncSetAttribute(gemm_tf32, cudaFuncAttributeMaxDynamicSharedMemorySize,
                         SMEM_TOTAL);

    k_abssum<<<256, 256>>>(w);
    k_scale<<<1, 1>>>();
    k_quant<<<(N_DIM * K_DIM) / 256, 256>>>(w);

    const int grid = (M / BM) * (N_DIM / BN);   // 512 * 8 = 4096
    gemm_tf32<<<grid, THREADS, SMEM_TOTAL>>>(x, bias, out);
}

// round 8
// speedup vs baseline: 2.3385x; 1.4215x over previous
#include <cuda_runtime.h>
#include <cuda_fp16.h>
#include <cstdint>

// ============================================================================
// QuantizedLinear: out = scale * (x @ S^T) + bias, S = sign(w)*(|w|>0.7*mean|w|)
// x [65536, 512] fp32, w [512, 512] fp32, bias [512] fp32, out [65536, 512] fp32
//
// R8: legacy tf32 mma.sync ceiling measured at ~134 TF/s (R3/R4/R7 all pin
// there). Switch to mma.sync.m16n8k16.f16 (2x MACs/instr, fp16 mantissa ==
// tf32 mantissa -> identical 2.1e-4 error). B stored as fp16 ternary (exact).
// A converted f32->f16x2 after LDS.64. 2-stage cp.async, 3 CTAs/SM.
// ============================================================================
#define K_DIM 512
#define N_DIM 512
#define BM 128
#define BN 64
#define BK 32
#define KT (K_DIM / BK)      // 16
#define THREADS 256

#define PAD_A 40             // fp32 words per A smem row (160B, conflict-free LDS.64)
#define PAD_B 40             // halves per B smem row (80B, conflict-free LDS.32)

#define A_STAGE_BYTES (BM * PAD_A * 4)                 // 20480
#define B_STAGE_BYTES (BN * PAD_B * 2)                 // 5120
#define STAGE_BYTES   (A_STAGE_BYTES + B_STAGE_BYTES)  // 25600
#define SMEM_TOTAL    (2 * STAGE_BYTES)                // 51200 -> 3 CTAs/SM

// Scratch (allocation-free)
__device__ __half  d_wq[N_DIM * K_DIM];
__device__ double  d_partial[256];
__device__ float   d_scale;
__device__ float   d_thresh;

// ============================================================================
// Prep kernels
// ============================================================================
__global__ void k_abssum(const float* __restrict__ w) {
    __shared__ double s[256];
    int b = blockIdx.x, t = threadIdx.x;
    const float* p = w + b * 1024;
    double acc = (double)fabsf(p[t]) + (double)fabsf(p[t + 256]) +
                 (double)fabsf(p[t + 512]) + (double)fabsf(p[t + 768]);
    s[t] = acc;
    __syncthreads();
    for (int o = 128; o > 0; o >>= 1) {
        if (t < o) s[t] += s[t + o];
        __syncthreads();
    }
    if (t == 0) d_partial[b] = s[0];
}

__global__ void k_scale() {
    double tot = 0.0;
    for (int i = 0; i < 256; i++) tot += d_partial[i];
    float sc = (float)(tot / (double)(N_DIM * K_DIM));
    if (sc < 1e-8f) sc = 1e-8f;
    d_scale = sc;
    d_thresh = 0.7f * sc;
}

__global__ void k_quant(const float* __restrict__ w) {
    int i = blockIdx.x * blockDim.x + threadIdx.x;
    float v = w[i];
    float th = d_thresh;
    float q = (fabsf(v) > th) ? (v > 0.0f ? 1.0f : -1.0f) : 0.0f;
    d_wq[i] = __float2half_rn(q);    // exact: {-1, 0, +1}
}

// ============================================================================
// Helpers
// ============================================================================
__device__ __forceinline__ uint32_t smem_u32(const void* p) {
    uint32_t a;
    asm("{ .reg .u64 t; cvta.to.shared.u64 t, %1; cvt.u32.u64 %0, t; }"
        : "=r"(a) : "l"(p));
    return a;
}

__device__ __forceinline__ void cp16(uint32_t saddr, const void* gaddr) {
    asm volatile("cp.async.cg.shared.global [%0], [%1], 16;"
                 :: "r"(saddr), "l"(gaddr) : "memory");
}

__device__ __forceinline__ void cp_commit() {
    asm volatile("cp.async.commit_group;" ::: "memory");
}

__device__ __forceinline__ void cp_wait0() {
    asm volatile("cp.async.wait_group 0;" ::: "memory");
}

// pack two f32 -> one f16x2 register: lo = first k, hi = second k
__device__ __forceinline__ uint32_t pack_h2(float lo, float hi) {
    uint32_t r;
    asm("cvt.rn.f16x2.f32 %0, %1, %2;" : "=r"(r) : "f"(hi), "f"(lo));
    return r;
}

__device__ __forceinline__ void mma_f16(float* c, uint32_t a0, uint32_t a1,
                                        uint32_t a2, uint32_t a3,
                                        uint32_t b0, uint32_t b1) {
    asm volatile(
        "mma.sync.aligned.m16n8k16.row.col.f32.f16.f16.f32 "
        "{%0,%1,%2,%3}, {%4,%5,%6,%7}, {%8,%9}, {%0,%1,%2,%3};"
        : "+f"(c[0]), "+f"(c[1]), "+f"(c[2]), "+f"(c[3])
        : "r"(a0), "r"(a1), "r"(a2), "r"(a3), "r"(b0), "r"(b1));
}

// ============================================================================
// Main GEMM: block 128x64, 8 warps (4M x 2N), warp tile 32x32, fp16 HMMA
// ============================================================================
__global__ void __launch_bounds__(THREADS, 3) gemm_f16(
    const float* __restrict__ x,
    const float* __restrict__ bias,
    float* __restrict__ out)
{
    extern __shared__ float smem[];
    const uint32_t sb = smem_u32(smem);
    const int tid = threadIdx.x;
    const int wid = tid >> 5;
    const int lane = tid & 31;
    const int grp = lane >> 2;     // 0..7
    const int qc = lane & 3;       // 0..3

    // 8 N-tiles of 64; consecutive bids share the M-tile (A L2 reuse)
    const int ntile = blockIdx.x & 7;
    const int mtile = blockIdx.x >> 3;
    const int m0 = mtile * BM;
    const int n0 = ntile * BN;

    const int warp_m = (wid & 3) * 32;          // 4 warps along M
    const int warp_n = (wid >> 2) * 32;         // 2 warps along N

    const __half* wq = d_wq;

    // ---- cp.async loader ----
    // A: 128 rows x 8 chunks (32 fp32) = 1024 chunks, 4/thread
    // B: 64 rows x 4 chunks (32 fp16)  = 256 chunks, 1/thread
    auto load_stage = [&](int s, int kt) {
        const uint32_t sA = sb + s * STAGE_BYTES;
        const uint32_t sB = sA + A_STAGE_BYTES;
        const int kk = kt * BK;
        #pragma unroll
        for (int i = 0; i < 4; i++) {
            int c = tid + i * THREADS;
            int row = c >> 3, cc = c & 7;
            cp16(sA + (uint32_t)row * (PAD_A * 4) + (uint32_t)cc * 16,
                 x + (size_t)(m0 + row) * K_DIM + kk + cc * 4);
        }
        {
            int row = tid >> 2, cc = tid & 3;
            cp16(sB + (uint32_t)row * (PAD_B * 2) + (uint32_t)cc * 16,
                 wq + (size_t)(n0 + row) * K_DIM + kk + cc * 8);
        }
    };

    float acc[2][4][4];
    #pragma unroll
    for (int i = 0; i < 2; i++)
        #pragma unroll
        for (int j = 0; j < 4; j++)
            #pragma unroll
            for (int r = 0; r < 4; r++) acc[i][j][r] = 0.0f;

    load_stage(0, 0);
    cp_commit();

    for (int kt = 0; kt < KT; kt++) {
        cp_wait0();                 // stage kt resident
        __syncthreads();            // all reads of kt-1 complete before reuse

        if (kt + 1 < KT) {          // overlap next load with compute(kt)
            load_stage((kt + 1) & 1, kt + 1);
            cp_commit();
        }

        const int s = kt & 1;
        const float* As = smem + s * (STAGE_BYTES / 4);
        const __half* Bs = (const __half*)(As + A_STAGE_BYTES / 4);

        #pragma unroll
        for (int ks = 0; ks < 2; ks++) {   // two k=16 steps
            const int k0 = ks * 16;

            // ---- A fragments: rows grp/grp+8, k pairs (2qc, 2qc+1) & +8 ----
            uint32_t a[2][4];
            #pragma unroll
            for (int tm = 0; tm < 2; tm++) {
                const float* ap0 = As + (warp_m + tm * 16 + grp) * PAD_A + k0 + 2 * qc;
                const float* ap1 = ap0 + 8 * PAD_A;
                float2 q0 = *reinterpret_cast<const float2*>(ap0);
                float2 q1 = *reinterpret_cast<const float2*>(ap1);
                float2 q2 = *reinterpret_cast<const float2*>(ap0 + 8);
                float2 q3 = *reinterpret_cast<const float2*>(ap1 + 8);
                a[tm][0] = pack_h2(q0.x, q0.y);
                a[tm][1] = pack_h2(q1.x, q1.y);
                a[tm][2] = pack_h2(q2.x, q2.y);
                a[tm][3] = pack_h2(q3.x, q3.y);
            }

            // ---- B fragments: col n=grp row group, halves (2qc,2qc+1) & +8 ----
            uint32_t b[4][2];
            #pragma unroll
            for (int tn = 0; tn < 4; tn++) {
                const __half* bp = Bs + (warp_n + tn * 8 + grp) * PAD_B + k0 + 2 * qc;
                b[tn][0] = *reinterpret_cast<const uint32_t*>(bp);
                b[tn][1] = *reinterpret_cast<const uint32_t*>(bp + 8);
            }

            #pragma unroll
            for (int tm = 0; tm < 2; tm++)
                #pragma unroll
                for (int tn = 0; tn < 4; tn++)
                    mma_f16(acc[tm][tn], a[tm][0], a[tm][1], a[tm][2], a[tm][3],
                            b[tn][0], b[tn][1]);
        }
    }

    // ---- Epilogue: out = scale*acc + bias ----
    const float scale = d_scale;
    #pragma unroll
    for (int tm = 0; tm < 2; tm++) {
        #pragma unroll
        for (int tn = 0; tn < 4; tn++) {
            const int row = m0 + warp_m + tm * 16 + grp;
            const int col = n0 + warp_n + tn * 8 + qc * 2;
            const float2 bv = *reinterpret_cast<const float2*>(bias + col);
            float2 v0, v1;
            v0.x = fmaf(scale, acc[tm][tn][0], bv.x);
            v0.y = fmaf(scale, acc[tm][tn][1], bv.y);
            v1.x = fmaf(scale, acc[tm][tn][2], bv.x);
            v1.y = fmaf(scale, acc[tm][tn][3], bv.y);
            *reinterpret_cast<float2*>(out + (size_t)row * N_DIM + col) = v0;
            *reinterpret_cast<float2*>(out + (size_t)(row + 8) * N_DIM + col) = v1;
        }
    }
}

// ============================================================================
// Host
// ============================================================================
extern "C" void kernel_launch(void* const* d_in, const int* in_sizes, int n_in,
                              void* d_out, int out_size) {
    const float* x    = (const float*)d_in[0];
    const float* w    = (const float*)d_in[1];
    const float* bias = (const float*)d_in[2];
    float* out        = (float*)d_out;
    const int M = in_sizes[0] / K_DIM;   // 65536

    cudaFuncSetAttribute(gemm_f16, cudaFuncAttributeMaxDynamicSharedMemorySize,
                         SMEM_TOTAL);

    k_abssum<<<256, 256>>>(w);
    k_scale<<<1, 1>>>();
    k_quant<<<(N_DIM * K_DIM) / 256, 256>>>(w);

    const int grid = (M / BM) * (N_DIM / BN);   // 512 * 8 = 4096
    gemm_f16<<<grid, THREADS, SMEM_TOTAL>>>(x, bias, out);
}

// round 9
// speedup vs baseline: 2.8328x; 1.2114x over previous
#include <cuda_runtime.h>
#include <cuda_fp16.h>
#include <cstdint>

// ============================================================================
// QuantizedLinear: out = scale * (x @ S^T) + bias, S = sign(w)*(|w|>0.7*mean|w|)
// x [65536, 512] fp32, w [512, 512] fp32, bias [512] fp32, out [65536, 512] fp32
//
// R9: all-fp16 GEMM. x converted once to fp16 (d_xh). A & B fp16 in smem with
// SW128 swizzle; fragments via ldmatrix.x4; mma.sync.m16n8k16.f16.
// BK=64, 2-stage cp.async, 3 CTAs/SM. (compute_103: no tcgen05.)
// ============================================================================
#define K_DIM 512
#define N_DIM 512
#define M_DIM 65536
#define BM 128
#define BN 64
#define BK 64
#define KT (K_DIM / BK)      // 8
#define THREADS 256

#define A_STAGE_BYTES (BM * BK * 2)                    // 16384 (128B rows, SW128)
#define B_STAGE_BYTES (BN * BK * 2)                    // 8192
#define STAGE_BYTES   (A_STAGE_BYTES + B_STAGE_BYTES)  // 24576
#define SMEM_TOTAL    (2 * STAGE_BYTES + 128)          // 49280 (+128 align pad)

// Scratch (allocation-free __device__ globals)
__device__ __half  d_xh[(size_t)M_DIM * K_DIM];        // 64 MB fp16 copy of x
__device__ __half  d_wq[N_DIM * K_DIM];
__device__ double  d_partial[256];
__device__ float   d_scale;
__device__ float   d_thresh;

// ============================================================================
// Prep kernels
// ============================================================================
__global__ void k_xconvert(const float* __restrict__ x) {
    size_t i = (size_t)blockIdx.x * blockDim.x + threadIdx.x;   // 8388608 threads
    const float4 v = reinterpret_cast<const float4*>(x)[i];
    __half2 h0 = __floats2half2_rn(v.x, v.y);
    __half2 h1 = __floats2half2_rn(v.z, v.w);
    uint2 o;
    o.x = *reinterpret_cast<uint32_t*>(&h0);
    o.y = *reinterpret_cast<uint32_t*>(&h1);
    reinterpret_cast<uint2*>(d_xh)[i] = o;
}

__global__ void k_abssum(const float* __restrict__ w) {
    __shared__ double s[256];
    int b = blockIdx.x, t = threadIdx.x;
    const float* p = w + b * 1024;
    double acc = (double)fabsf(p[t]) + (double)fabsf(p[t + 256]) +
                 (double)fabsf(p[t + 512]) + (double)fabsf(p[t + 768]);
    s[t] = acc;
    __syncthreads();
    for (int o = 128; o > 0; o >>= 1) {
        if (t < o) s[t] += s[t + o];
        __syncthreads();
    }
    if (t == 0) d_partial[b] = s[0];
}

__global__ void k_scale() {
    double tot = 0.0;
    for (int i = 0; i < 256; i++) tot += d_partial[i];
    float sc = (float)(tot / (double)(N_DIM * K_DIM));
    if (sc < 1e-8f) sc = 1e-8f;
    d_scale = sc;
    d_thresh = 0.7f * sc;
}

__global__ void k_quant(const float* __restrict__ w) {
    int i = blockIdx.x * blockDim.x + threadIdx.x;
    float v = w[i];
    float th = d_thresh;
    float q = (fabsf(v) > th) ? (v > 0.0f ? 1.0f : -1.0f) : 0.0f;
    d_wq[i] = __float2half_rn(q);    // exact in fp16
}

// ============================================================================
// Helpers
// ============================================================================
__device__ __forceinline__ uint32_t smem_u32(const void* p) {
    uint32_t a;
    asm("{ .reg .u64 t; cvta.to.shared.u64 t, %1; cvt.u32.u64 %0, t; }"
        : "=r"(a) : "l"(p));
    return a;
}

__device__ __forceinline__ void cp16(uint32_t saddr, const void* gaddr) {
    asm volatile("cp.async.cg.shared.global [%0], [%1], 16;"
                 :: "r"(saddr), "l"(gaddr) : "memory");
}

__device__ __forceinline__ void cp_commit() {
    asm volatile("cp.async.commit_group;" ::: "memory");
}

__device__ __forceinline__ void cp_wait0() {
    asm volatile("cp.async.wait_group 0;" ::: "memory");
}

__device__ __forceinline__ void ldsm_x4(uint32_t& r0, uint32_t& r1,
                                        uint32_t& r2, uint32_t& r3,
                                        uint32_t addr) {
    asm volatile("ldmatrix.sync.aligned.m8n8.x4.shared.b16 {%0,%1,%2,%3}, [%4];"
                 : "=r"(r0), "=r"(r1), "=r"(r2), "=r"(r3) : "r"(addr));
}

__device__ __forceinline__ void mma_f16(float* c, uint32_t a0, uint32_t a1,
                                        uint32_t a2, uint32_t a3,
                                        uint32_t b0, uint32_t b1) {
    asm volatile(
        "mma.sync.aligned.m16n8k16.row.col.f32.f16.f16.f32 "
        "{%0,%1,%2,%3}, {%4,%5,%6,%7}, {%8,%9}, {%0,%1,%2,%3};"
        : "+f"(c[0]), "+f"(c[1]), "+f"(c[2]), "+f"(c[3])
        : "r"(a0), "r"(a1), "r"(a2), "r"(a3), "r"(b0), "r"(b1));
}

// ============================================================================
// Main GEMM: block 128x64, 8 warps (4M x 2N), warp tile 32x32, fp16 ldmatrix
// SW128 layout: 128B rows, 16B chunk c stored at position c ^ (row & 7).
// ============================================================================
__global__ void __launch_bounds__(THREADS, 3) gemm_f16(
    const float* __restrict__ bias,
    float* __restrict__ out)
{
    extern __shared__ char smem[];
    // 128B-align the base so swizzle XOR arithmetic owns bits [4:7)
    const uint32_t sb = (smem_u32(smem) + 127u) & ~127u;
    const int tid = threadIdx.x;
    const int wid = tid >> 5;
    const int lane = tid & 31;
    const int grp = lane >> 2;
    const int qc = lane & 3;

    const int ntile = blockIdx.x & 7;       // consecutive bids share M-tile
    const int mtile = blockIdx.x >> 3;
    const int m0 = mtile * BM;
    const int n0 = ntile * BN;

    const int warp_m = (wid & 3) * 32;      // 4 warps along M
    const int warp_n = (wid >> 2) * 32;     // 2 warps along N

    const __half* xh = d_xh;
    const __half* wq = d_wq;

    // ---- cp.async loader with SW128 swizzle ----
    // A: 128 rows x 8 chunks = 1024 (4/thread); B: 64 x 8 = 512 (2/thread)
    auto load_stage = [&](int s, int kt) {
        const uint32_t sA = sb + s * STAGE_BYTES;
        const uint32_t sB = sA + A_STAGE_BYTES;
        const int kk = kt * BK;
        #pragma unroll
        for (int i = 0; i < 4; i++) {
            int c_lin = tid + i * THREADS;
            int row = c_lin >> 3, c = c_lin & 7;
            cp16(sA + (uint32_t)row * 128 + (uint32_t)((c ^ (row & 7)) << 4),
                 xh + (size_t)(m0 + row) * K_DIM + kk + c * 8);
        }
        #pragma unroll
        for (int i = 0; i < 2; i++) {
            int c_lin = tid + i * THREADS;
            int row = c_lin >> 3, c = c_lin & 7;
            cp16(sB + (uint32_t)row * 128 + (uint32_t)((c ^ (row & 7)) << 4),
                 wq + (size_t)(n0 + row) * K_DIM + kk + c * 8);
        }
    };

    // ---- ldmatrix per-lane base addresses (relative to stage base) ----
    // A x4 for tm: T0 rows+0..7 kh0, T1 rows+8 kh0, T2 rows+0 kh1, T3 rows+8 kh1
    const int lt = lane >> 3;               // tile index 0..3
    const int lr = lane & 7;                // row within tile
    uint32_t baseA[2], baseB[2];
    {
        const int rowoffA = (lt & 1) * 8;
        const int khA = lt >> 1;
        #pragma unroll
        for (int tm = 0; tm < 2; tm++) {
            int row = warp_m + tm * 16 + rowoffA + lr;
            baseA[tm] = (uint32_t)row * 128 + (uint32_t)((khA ^ lr) << 4);
        }
        // B x4 for tnp: T0 n+0..7 kh0, T1 n+0..7 kh1, T2 n+8 kh0, T3 n+8 kh1
        const int rowoffB = (lt >> 1) * 8;
        const int khB = lt & 1;
        #pragma unroll
        for (int tnp = 0; tnp < 2; tnp++) {
            int row = warp_n + tnp * 16 + rowoffB + lr;
            baseB[tnp] = (uint32_t)A_STAGE_BYTES +
                         (uint32_t)row * 128 + (uint32_t)((khB ^ lr) << 4);
        }
    }

    float acc[2][4][4];
    #pragma unroll
    for (int i = 0; i < 2; i++)
        #pragma unroll
        for (int j = 0; j < 4; j++)
            #pragma unroll
            for (int r = 0; r < 4; r++) acc[i][j][r] = 0.0f;

    load_stage(0, 0);
    cp_commit();

    for (int kt = 0; kt < KT; kt++) {
        cp_wait0();
        __syncthreads();            // stage kt visible; other stage's reads done

        if (kt + 1 < KT) {
            load_stage((kt + 1) & 1, kt + 1);
            cp_commit();
        }

        const uint32_t sStage = sb + (uint32_t)(kt & 1) * STAGE_BYTES;
        const uint32_t a0base = sStage + baseA[0];
        const uint32_t a1base = sStage + baseA[1];
        const uint32_t b0base = sStage + baseB[0];
        const uint32_t b1base = sStage + baseB[1];

        #pragma unroll
        for (int ks = 0; ks < 4; ks++) {    // four k=16 steps
            const uint32_t kx = (uint32_t)ks << 5;   // chunk pair XOR offset

            uint32_t a[2][4];
            ldsm_x4(a[0][0], a[0][1], a[0][2], a[0][3], a0base ^ kx);
            ldsm_x4(a[1][0], a[1][1], a[1][2], a[1][3], a1base ^ kx);

            uint32_t b[4][2];
            ldsm_x4(b[0][0], b[0][1], b[1][0], b[1][1], b0base ^ kx);
            ldsm_x4(b[2][0], b[2][1], b[3][0], b[3][1], b1base ^ kx);

            #pragma unroll
            for (int tm = 0; tm < 2; tm++)
                #pragma unroll
                for (int tn = 0; tn < 4; tn++)
                    mma_f16(acc[tm][tn], a[tm][0], a[tm][1], a[tm][2], a[tm][3],
                            b[tn][0], b[tn][1]);
        }
    }

    // ---- Epilogue: out = scale*acc + bias ----
    const float scale = d_scale;
    #pragma unroll
    for (int tm = 0; tm < 2; tm++) {
        #pragma unroll
        for (int tn = 0; tn < 4; tn++) {
            const int row = m0 + warp_m + tm * 16 + grp;
            const int col = n0 + warp_n + tn * 8 + qc * 2;
            const float2 bv = *reinterpret_cast<const float2*>(bias + col);
            float2 v0, v1;
            v0.x = fmaf(scale, acc[tm][tn][0], bv.x);
            v0.y = fmaf(scale, acc[tm][tn][1], bv.y);
            v1.x = fmaf(scale, acc[tm][tn][2], bv.x);
            v1.y = fmaf(scale, acc[tm][tn][3], bv.y);
            *reinterpret_cast<float2*>(out + (size_t)row * N_DIM + col) = v0;
            *reinterpret_cast<float2*>(out + (size_t)(row + 8) * N_DIM + col) = v1;
        }
    }
}

// ============================================================================
// Host
// ============================================================================
extern "C" void kernel_launch(void* const* d_in, const int* in_sizes, int n_in,
                              void* d_out, int out_size) {
    const float* x    = (const float*)d_in[0];
    const float* w    = (const float*)d_in[1];
    const float* bias = (const float*)d_in[2];
    float* out        = (float*)d_out;
    const int M = in_sizes[0] / K_DIM;   // 65536

    cudaFuncSetAttribute(gemm_f16, cudaFuncAttributeMaxDynamicSharedMemorySize,
                         SMEM_TOTAL);

    k_xconvert<<<(int)(((size_t)M * K_DIM / 4) / 256), 256>>>(x);
    k_abssum<<<256, 256>>>(w);
    k_scale<<<1, 1>>>();
    k_quant<<<(N_DIM * K_DIM) / 256, 256>>>(w);

    const int grid = (M / BM) * (N_DIM / BN);   // 512 * 8 = 4096
    gemm_f16<<<grid, THREADS, SMEM_TOTAL>>>(bias, out);
}